// round 1
// baseline (speedup 1.0000x reference)
#include <cuda_runtime.h>

// VQ-VAE vector quantizer forward.
// Inputs: d_in[0] = z_e [65536, 256] f32, d_in[1] = emb_w [2048, 256] f32.
// Output buffer (f32), assumed layout = flattened tuple in reference order:
//   [0, 65536*256)        z_q_st  (== emb_w[argmin], forward value)
//   [65536*256]           vq_loss (scalar)
//   [65536*256+1, +65536) encoding_indices (cast to float)

#define M_ROWS  65536
#define K_CODES 2048
#define D_DIM   256

#define BM 128
#define BN 64
#define BK 32
#define TM 8
#define TN 4
#define NTHREADS 256

__device__ float  g_zsq[M_ROWS];
__device__ float  g_esq[K_CODES];
__device__ double g_loss;

// ---------------------------------------------------------------------------
// Row sum-of-squares, one warp per row: lane-strided partials + butterfly.
// ---------------------------------------------------------------------------
__global__ void zsq_kernel(const float* __restrict__ x) {
    int warp = (blockIdx.x * blockDim.x + threadIdx.x) >> 5;
    int lane = threadIdx.x & 31;
    if (warp >= M_ROWS) return;
    const float* r = x + (size_t)warp * D_DIM;
    float s = 0.f;
#pragma unroll
    for (int i = 0; i < D_DIM / 32; i++) {
        float v = r[lane + 32 * i];
        s = fmaf(v, v, s);
    }
#pragma unroll
    for (int o = 16; o; o >>= 1) s += __shfl_xor_sync(0xffffffffu, s, o);
    if (lane == 0) g_zsq[warp] = s;
}

__global__ void esq_kernel(const float* __restrict__ x) {
    int warp = (blockIdx.x * blockDim.x + threadIdx.x) >> 5;
    int lane = threadIdx.x & 31;
    if (blockIdx.x == 0 && threadIdx.x == 0) g_loss = 0.0;  // re-zero every replay
    if (warp >= K_CODES) return;
    const float* r = x + (size_t)warp * D_DIM;
    float s = 0.f;
#pragma unroll
    for (int i = 0; i < D_DIM / 32; i++) {
        float v = r[lane + 32 * i];
        s = fmaf(v, v, s);
    }
#pragma unroll
    for (int o = 16; o; o >>= 1) s += __shfl_xor_sync(0xffffffffu, s, o);
    if (lane == 0) g_esq[warp] = s;
}

// ---------------------------------------------------------------------------
// Fused distance GEMM + argmin + gather + loss partial.
// Block: BM=128 z-rows. Loops over all K_CODES in BN=64 tiles, BK=32 k-tiles.
// 256 threads, 8x4 register micro-tile. fp32 throughout; distance evaluated
// exactly like the reference: d = fl(fl(z_sq + e_sq) - 2*cross).
// ---------------------------------------------------------------------------
__global__ __launch_bounds__(NTHREADS) void vq_main_kernel(
    const float* __restrict__ Z, const float* __restrict__ E,
    float* __restrict__ out) {

    __shared__ float As[BK][BM];     // 16 KB  (k-major, m-minor)
    __shared__ float Bs[BK][BN];     //  8 KB
    __shared__ float red_v[16][BM];  //  8 KB
    __shared__ int   red_i[16][BM];  //  8 KB
    __shared__ int   idx_s[BM];
    __shared__ float wsum[NTHREADS / 32];

    const int t   = threadIdx.x;
    const int tx  = t & 15;
    const int ty  = t >> 4;
    const int m0  = blockIdx.x * BM;
    const int row0 = ty * TM;
    const int col0 = tx * TN;

    const float4* Zf4 = (const float4*)Z;
    const float4* Ef4 = (const float4*)E;

    float zs[TM];
#pragma unroll
    for (int r = 0; r < TM; r++) zs[r] = g_zsq[m0 + row0 + r];

    float bestv[TM];
    int   besti[TM];
#pragma unroll
    for (int r = 0; r < TM; r++) { bestv[r] = 3.4e38f; besti[r] = 0; }

    for (int nt = 0; nt < K_CODES / BN; nt++) {
        const int n0 = nt * BN;
        float acc[TM][TN];
#pragma unroll
        for (int r = 0; r < TM; r++)
#pragma unroll
            for (int c = 0; c < TN; c++) acc[r][c] = 0.f;

        for (int kt = 0; kt < D_DIM / BK; kt++) {
            __syncthreads();
            // Stage A tile: 128 rows x 32 k = 1024 float4, 4 per thread,
            // transposed into As[k][m].
#pragma unroll
            for (int i = 0; i < 4; i++) {
                int idx = t + i * NTHREADS;
                int m  = idx >> 3;          // BK/4 = 8 float4 per row-chunk
                int kq = idx & 7;
                float4 v = Zf4[(size_t)(m0 + m) * (D_DIM / 4) + kt * (BK / 4) + kq];
                As[kq * 4 + 0][m] = v.x;
                As[kq * 4 + 1][m] = v.y;
                As[kq * 4 + 2][m] = v.z;
                As[kq * 4 + 3][m] = v.w;
            }
            // Stage B tile: 64 codewords x 32 k = 512 float4, 2 per thread.
#pragma unroll
            for (int i = 0; i < 2; i++) {
                int idx = t + i * NTHREADS;
                int n  = idx >> 3;
                int kq = idx & 7;
                float4 v = Ef4[(size_t)(n0 + n) * (D_DIM / 4) + kt * (BK / 4) + kq];
                Bs[kq * 4 + 0][n] = v.x;
                Bs[kq * 4 + 1][n] = v.y;
                Bs[kq * 4 + 2][n] = v.z;
                Bs[kq * 4 + 3][n] = v.w;
            }
            __syncthreads();

#pragma unroll
            for (int k = 0; k < BK; k++) {
                float a[TM], b[TN];
#pragma unroll
                for (int r = 0; r < TM; r++) a[r] = As[k][row0 + r];
#pragma unroll
                for (int c = 0; c < TN; c++) b[c] = Bs[k][col0 + c];
#pragma unroll
                for (int r = 0; r < TM; r++)
#pragma unroll
                    for (int c = 0; c < TN; c++)
                        acc[r][c] = fmaf(a[r], b[c], acc[r][c]);
            }
        }

        // Distances + local argmin (ascending n; strict < keeps first index,
        // matching jnp.argmin tie-breaking).
#pragma unroll
        for (int c = 0; c < TN; c++) {
            int n = n0 + col0 + c;
            float esq = g_esq[n];
#pragma unroll
            for (int r = 0; r < TM; r++) {
                float s = zs[r] + esq;           // rounded, like reference
                float d = fmaf(-2.0f, acc[r][c], s);  // == fl(s - 2*acc), 2*acc exact
                if (d < bestv[r]) { bestv[r] = d; besti[r] = n; }
            }
        }
    }

    // Cross-thread argmin per row (explicit index tie-break -> lowest index).
#pragma unroll
    for (int r = 0; r < TM; r++) {
        red_v[tx][row0 + r] = bestv[r];
        red_i[tx][row0 + r] = besti[r];
    }
    __syncthreads();
    if (t < BM) {
        float bv = red_v[0][t];
        int   bi = red_i[0][t];
#pragma unroll
        for (int x = 1; x < 16; x++) {
            float v = red_v[x][t];
            int   i = red_i[x][t];
            if (v < bv || (v == bv && i < bi)) { bv = v; bi = i; }
        }
        idx_s[t] = bi;
        out[(size_t)M_ROWS * D_DIM + 1 + m0 + t] = (float)bi;
    }
    __syncthreads();

    // Gather z_q into output + loss partial sum.
    float4* Of4 = (float4*)out;
    float part = 0.f;
    for (int i = t; i < BM * (D_DIM / 4); i += NTHREADS) {
        int m = i >> 6;   // 64 float4 per row
        int c = i & 63;
        int bi = idx_s[m];
        float4 e = Ef4[(size_t)bi * (D_DIM / 4) + c];
        float4 z = Zf4[(size_t)(m0 + m) * (D_DIM / 4) + c];
        Of4[(size_t)(m0 + m) * (D_DIM / 4) + c] = e;
        float dx = e.x - z.x, dy = e.y - z.y, dz = e.z - z.z, dw = e.w - z.w;
        part = fmaf(dx, dx, part);
        part = fmaf(dy, dy, part);
        part = fmaf(dz, dz, part);
        part = fmaf(dw, dw, part);
    }
#pragma unroll
    for (int o = 16; o; o >>= 1) part += __shfl_xor_sync(0xffffffffu, part, o);
    if ((t & 31) == 0) wsum[t >> 5] = part;
    __syncthreads();
    if (t == 0) {
        float s = 0.f;
#pragma unroll
        for (int w = 0; w < NTHREADS / 32; w++) s += wsum[w];
        atomicAdd(&g_loss, (double)s);
    }
}

__global__ void finalize_kernel(float* __restrict__ out) {
    out[(size_t)M_ROWS * D_DIM] =
        (float)(1.25 * g_loss / ((double)M_ROWS * (double)D_DIM));
}

// ---------------------------------------------------------------------------
extern "C" void kernel_launch(void* const* d_in, const int* in_sizes, int n_in,
                              void* d_out, int out_size) {
    (void)in_sizes; (void)n_in; (void)out_size;
    const float* z = (const float*)d_in[0];
    const float* e = (const float*)d_in[1];
    float* out = (float*)d_out;

    // 8 warps per block -> 8 rows per block.
    zsq_kernel<<<M_ROWS / 8, 256>>>(z);
    esq_kernel<<<K_CODES / 8, 256>>>(e);
    vq_main_kernel<<<M_ROWS / BM, NTHREADS>>>(z, e, out);
    finalize_kernel<<<1, 1>>>(out);
}

// round 2
// speedup vs baseline: 1.4579x; 1.4579x over previous
#include <cuda_runtime.h>

// VQ-VAE vector quantizer forward — fp32-exact, packed FFMA2 (fma.rn.f32x2).
// Inputs: d_in[0] = z_e [65536, 256] f32, d_in[1] = emb_w [2048, 256] f32.
// Output f32 buffer:
//   [0, 65536*256)        z_q_st  (== emb_w[argmin])
//   [65536*256]           vq_loss
//   [65536*256+1, +65536) encoding_indices (as float)

#define M_ROWS  65536
#define K_CODES 2048
#define D_DIM   256

#define BM 128
#define BN 128
#define BK 32
#define NTHREADS 256
#define PAD 4

__device__ float  g_zsq[M_ROWS];
__device__ float  g_esq[K_CODES];
__device__ double g_loss;

typedef unsigned long long ull;

__device__ __forceinline__ void ffma2(ull& d, ull a, ull b) {
    asm("fma.rn.f32x2 %0, %1, %2, %0;" : "+l"(d) : "l"(a), "l"(b));
}
__device__ __forceinline__ ull dup2(float x) {
    ull r; asm("mov.b64 %0, {%1, %1};" : "=l"(r) : "f"(x)); return r;
}
__device__ __forceinline__ void unpack2(float& lo, float& hi, ull p) {
    asm("mov.b64 {%0, %1}, %2;" : "=f"(lo), "=f"(hi) : "l"(p));
}

// ---------------------------------------------------------------------------
__global__ void zsq_kernel(const float* __restrict__ x) {
    int warp = (blockIdx.x * blockDim.x + threadIdx.x) >> 5;
    int lane = threadIdx.x & 31;
    if (warp >= M_ROWS) return;
    const float* r = x + (size_t)warp * D_DIM;
    float s = 0.f;
#pragma unroll
    for (int i = 0; i < D_DIM / 32; i++) { float v = r[lane + 32 * i]; s = fmaf(v, v, s); }
#pragma unroll
    for (int o = 16; o; o >>= 1) s += __shfl_xor_sync(0xffffffffu, s, o);
    if (lane == 0) g_zsq[warp] = s;
}

__global__ void esq_kernel(const float* __restrict__ x) {
    int warp = (blockIdx.x * blockDim.x + threadIdx.x) >> 5;
    int lane = threadIdx.x & 31;
    if (blockIdx.x == 0 && threadIdx.x == 0) g_loss = 0.0;   // re-zero each replay
    if (warp >= K_CODES) return;
    const float* r = x + (size_t)warp * D_DIM;
    float s = 0.f;
#pragma unroll
    for (int i = 0; i < D_DIM / 32; i++) { float v = r[lane + 32 * i]; s = fmaf(v, v, s); }
#pragma unroll
    for (int o = 16; o; o >>= 1) s += __shfl_xor_sync(0xffffffffu, s, o);
    if (lane == 0) g_esq[warp] = s;
}

// ---------------------------------------------------------------------------
// Fused distance GEMM (FFMA2) + argmin + gather + loss partial.
// Block: 128 z-rows. Thread grid 16x16, micro-tile 8x8 split into 4-row/4-col
// groups at offsets {ty*4, 64+ty*4} x {tx*4, 64+tx*4}. Accumulators packed
// along M as f32x2 pairs. fp32 throughout; distance evaluated exactly like
// the reference: d = fl(fl(z_sq + e_sq) - 2*cross).
// ---------------------------------------------------------------------------
__global__ __launch_bounds__(NTHREADS, 2) void vq_main_kernel(
    const float* __restrict__ Z, const float* __restrict__ E,
    float* __restrict__ out) {

    __shared__ float As[BK][BM + PAD];   // k-major, m-minor
    __shared__ float Bs[BK][BN + PAD];
    __shared__ int   idx_s[BM];
    __shared__ float wsum[NTHREADS / 32];

    const int t  = threadIdx.x;
    const int tx = t & 15;
    const int ty = t >> 4;
    const int m0 = blockIdx.x * BM;

    const float4* Zf4 = (const float4*)Z;
    const float4* Ef4 = (const float4*)E;

    // thread rows j=0..7 -> global row offset within block:
    //   j<4: ty*4+j   j>=4: 64+ty*4+(j-4)
    float zs[8];
#pragma unroll
    for (int j = 0; j < 8; j++) {
        int r = (j < 4) ? (ty * 4 + j) : (64 + ty * 4 + (j - 4));
        zs[j] = g_zsq[m0 + r];
    }

    float bestv[8];
    int   besti[8];
#pragma unroll
    for (int j = 0; j < 8; j++) { bestv[j] = 3.4e38f; besti[j] = 0; }

    for (int nt = 0; nt < K_CODES / BN; nt++) {
        const int n0 = nt * BN;

        ull acc[4][8];   // acc[rp][c]: row-pair rp (rows 2rp,2rp+1 of j-index), col c
#pragma unroll
        for (int rp = 0; rp < 4; rp++)
#pragma unroll
            for (int c = 0; c < 8; c++) acc[rp][c] = 0ull;

        for (int kt = 0; kt < D_DIM / BK; kt++) {
            __syncthreads();
            // Stage A: 128 rows x 32 k = 1024 float4, transpose into As[k][m].
#pragma unroll
            for (int i = 0; i < 4; i++) {
                int idx = t + i * NTHREADS;
                int m = idx >> 3, kq = idx & 7;
                float4 v = Zf4[(size_t)(m0 + m) * (D_DIM / 4) + kt * (BK / 4) + kq];
                As[kq * 4 + 0][m] = v.x;
                As[kq * 4 + 1][m] = v.y;
                As[kq * 4 + 2][m] = v.z;
                As[kq * 4 + 3][m] = v.w;
            }
            // Stage B: 128 codes x 32 k = 1024 float4, transpose into Bs[k][n].
#pragma unroll
            for (int i = 0; i < 4; i++) {
                int idx = t + i * NTHREADS;
                int n = idx >> 3, kq = idx & 7;
                float4 v = Ef4[(size_t)(n0 + n) * (D_DIM / 4) + kt * (BK / 4) + kq];
                Bs[kq * 4 + 0][n] = v.x;
                Bs[kq * 4 + 1][n] = v.y;
                Bs[kq * 4 + 2][n] = v.z;
                Bs[kq * 4 + 3][n] = v.w;
            }
            __syncthreads();

#pragma unroll
            for (int k = 0; k < BK; k++) {
                // a pairs come packed for free from LDS.128
                ulonglong2 A0 = *(const ulonglong2*)&As[k][ty * 4];        // (j0,j1),(j2,j3)
                ulonglong2 A1 = *(const ulonglong2*)&As[k][64 + ty * 4];   // (j4,j5),(j6,j7)
                float4 b0 = *(const float4*)&Bs[k][tx * 4];
                float4 b1 = *(const float4*)&Bs[k][64 + tx * 4];
                ull ap[4] = { A0.x, A0.y, A1.x, A1.y };
                ull bd[8] = { dup2(b0.x), dup2(b0.y), dup2(b0.z), dup2(b0.w),
                              dup2(b1.x), dup2(b1.y), dup2(b1.z), dup2(b1.w) };
#pragma unroll
                for (int rp = 0; rp < 4; rp++)
#pragma unroll
                    for (int c = 0; c < 8; c++)
                        ffma2(acc[rp][c], ap[rp], bd[c]);
            }
        }

        // Distances + per-thread argmin. Column order is ascending in n
        // (tx*4+c then 64+tx*4+c), strict < keeps first (lowest) index.
#pragma unroll
        for (int c = 0; c < 8; c++) {
            int n = n0 + ((c < 4) ? (tx * 4 + c) : (64 + tx * 4 + (c - 4)));
            float esq = g_esq[n];
#pragma unroll
            for (int rp = 0; rp < 4; rp++) {
                float xlo, xhi;
                unpack2(xlo, xhi, acc[rp][c]);
                int jlo = rp * 2, jhi = rp * 2 + 1;
                float slo = zs[jlo] + esq;                 // rounded, like reference
                float dlo = fmaf(-2.0f, xlo, slo);         // == fl(s - 2*cross)
                if (dlo < bestv[jlo]) { bestv[jlo] = dlo; besti[jlo] = n; }
                float shi = zs[jhi] + esq;
                float dhi = fmaf(-2.0f, xhi, shi);
                if (dhi < bestv[jhi]) { bestv[jhi] = dhi; besti[jhi] = n; }
            }
        }
    }

    // Cross-thread argmin: the 16 tx-lanes sharing a row live in one half-warp.
    // Butterfly with index tie-break -> global lowest index on ties.
#pragma unroll
    for (int j = 0; j < 8; j++) {
        float v = bestv[j];
        int   i = besti[j];
#pragma unroll
        for (int off = 8; off; off >>= 1) {
            float ov = __shfl_xor_sync(0xffffffffu, v, off);
            int   oi = __shfl_xor_sync(0xffffffffu, i, off);
            if (ov < v || (ov == v && oi < i)) { v = ov; i = oi; }
        }
        if (tx == 0) {
            int r = (j < 4) ? (ty * 4 + j) : (64 + ty * 4 + (j - 4));
            idx_s[r] = i;
            out[(size_t)M_ROWS * D_DIM + 1 + m0 + r] = (float)i;
        }
    }
    __syncthreads();

    // Gather z_q into output + loss partial.
    float4* Of4 = (float4*)out;
    float part = 0.f;
    for (int i = t; i < BM * (D_DIM / 4); i += NTHREADS) {
        int m = i >> 6;
        int c = i & 63;
        int bi = idx_s[m];
        float4 e = Ef4[(size_t)bi * (D_DIM / 4) + c];
        float4 z = Zf4[(size_t)(m0 + m) * (D_DIM / 4) + c];
        Of4[(size_t)(m0 + m) * (D_DIM / 4) + c] = e;
        float dx = e.x - z.x, dy = e.y - z.y, dz = e.z - z.z, dw = e.w - z.w;
        part = fmaf(dx, dx, part);
        part = fmaf(dy, dy, part);
        part = fmaf(dz, dz, part);
        part = fmaf(dw, dw, part);
    }
#pragma unroll
    for (int o = 16; o; o >>= 1) part += __shfl_xor_sync(0xffffffffu, part, o);
    if ((t & 31) == 0) wsum[t >> 5] = part;
    __syncthreads();
    if (t == 0) {
        float s = 0.f;
#pragma unroll
        for (int w = 0; w < NTHREADS / 32; w++) s += wsum[w];
        atomicAdd(&g_loss, (double)s);
    }
}

__global__ void finalize_kernel(float* __restrict__ out) {
    out[(size_t)M_ROWS * D_DIM] =
        (float)(1.25 * g_loss / ((double)M_ROWS * (double)D_DIM));
}

// ---------------------------------------------------------------------------
extern "C" void kernel_launch(void* const* d_in, const int* in_sizes, int n_in,
                              void* d_out, int out_size) {
    (void)in_sizes; (void)n_in; (void)out_size;
    const float* z = (const float*)d_in[0];
    const float* e = (const float*)d_in[1];
    float* out = (float*)d_out;

    zsq_kernel<<<M_ROWS / 8, 256>>>(z);
    esq_kernel<<<K_CODES / 8, 256>>>(e);
    vq_main_kernel<<<M_ROWS / BM, NTHREADS>>>(z, e, out);
    finalize_kernel<<<1, 1>>>(out);
}

// round 5
// speedup vs baseline: 3.3342x; 2.2869x over previous
#include <cuda_runtime.h>
#include <cuda_bf16.h>
#include <cstdint>

// VQ-VAE quantizer — split-precision bf16 GEMM via mma.sync.m16n8k16 (HMMA).
// cross = Zh·Eh^T + Zh·El^T + Zl·Eh^T (bf16 in, fp32 accum)
// d = fl( fl(zsq+esq) - 2*cross ), argmin compared on rounded fp32 d.

#define M_ROWS  65536
#define K_CODES 2048
#define D_DIM   256
#define BM      128
#define BN      128
#define NCHUNK  (K_CODES / BN)   // 16
#define NTHREADS 256

// smem layout (dynamic)
#define OFF_ESQ   0        // 2048 floats = 8192 B
#define OFF_REDV  8192     // [4][128] float = 2048
#define OFF_REDI  10240    // [4][128] int   = 2048
#define OFF_IDX   12288    // 128 int
#define OFF_WSUM  12800    // 8 float
#define OFF_A     16384    // Ah 64KB
#define OFF_AL    81920    // Al 64KB
#define OFF_B     147456   // 2 bufs x (Bh 16KB + Bl 16KB) = 64KB
#define SMEM_BYTES 212992

__device__ float  g_zsq[M_ROWS];
__device__ float  g_esq[K_CODES];
__device__ double g_loss;
__device__ __nv_bfloat16 g_Zh[(size_t)M_ROWS * D_DIM];
__device__ __nv_bfloat16 g_Zl[(size_t)M_ROWS * D_DIM];
__device__ __nv_bfloat16 g_Eh[(size_t)K_CODES * D_DIM];
__device__ __nv_bfloat16 g_El[(size_t)K_CODES * D_DIM];

__device__ __forceinline__ uint32_t smem_u32(const void* p) {
    uint32_t a;
    asm("{ .reg .u64 t; cvta.to.shared.u64 t, %1; cvt.u32.u64 %0, t; }" : "=r"(a) : "l"(p));
    return a;
}
__device__ __forceinline__ void ldsm_x4(uint32_t& r0, uint32_t& r1, uint32_t& r2,
                                        uint32_t& r3, uint32_t addr) {
    asm volatile("ldmatrix.sync.aligned.m8n8.x4.shared.b16 {%0,%1,%2,%3}, [%4];"
                 : "=r"(r0), "=r"(r1), "=r"(r2), "=r"(r3) : "r"(addr));
}
__device__ __forceinline__ void ldsm_x2(uint32_t& r0, uint32_t& r1, uint32_t addr) {
    asm volatile("ldmatrix.sync.aligned.m8n8.x2.shared.b16 {%0,%1}, [%2];"
                 : "=r"(r0), "=r"(r1) : "r"(addr));
}
__device__ __forceinline__ void mma16816(float* c, const uint32_t* a, const uint32_t* b) {
    asm volatile("mma.sync.aligned.m16n8k16.row.col.f32.bf16.bf16.f32 "
                 "{%0,%1,%2,%3}, {%4,%5,%6,%7}, {%8,%9}, {%0,%1,%2,%3};"
                 : "+f"(c[0]), "+f"(c[1]), "+f"(c[2]), "+f"(c[3])
                 : "r"(a[0]), "r"(a[1]), "r"(a[2]), "r"(a[3]), "r"(b[0]), "r"(b[1]));
}

// ---------------- pre-kernels ----------------
__global__ void split_z_kernel(const float* __restrict__ z) {
    size_t i = ((size_t)blockIdx.x * 256 + threadIdx.x) * 4;
    float4 v = *(const float4*)(z + i);
    __nv_bfloat16 h0 = __float2bfloat16(v.x), h1 = __float2bfloat16(v.y);
    __nv_bfloat16 h2 = __float2bfloat16(v.z), h3 = __float2bfloat16(v.w);
    __nv_bfloat16 l0 = __float2bfloat16(v.x - __bfloat162float(h0));
    __nv_bfloat16 l1 = __float2bfloat16(v.y - __bfloat162float(h1));
    __nv_bfloat16 l2 = __float2bfloat16(v.z - __bfloat162float(h2));
    __nv_bfloat16 l3 = __float2bfloat16(v.w - __bfloat162float(h3));
    ((__nv_bfloat162*)g_Zh)[i / 2]     = __nv_bfloat162(h0, h1);
    ((__nv_bfloat162*)g_Zh)[i / 2 + 1] = __nv_bfloat162(h2, h3);
    ((__nv_bfloat162*)g_Zl)[i / 2]     = __nv_bfloat162(l0, l1);
    ((__nv_bfloat162*)g_Zl)[i / 2 + 1] = __nv_bfloat162(l2, l3);
}
__global__ void split_e_kernel(const float* __restrict__ e) {
    if (blockIdx.x == 0 && threadIdx.x == 0) g_loss = 0.0;
    size_t i = ((size_t)blockIdx.x * 256 + threadIdx.x) * 4;
    float4 v = *(const float4*)(e + i);
    __nv_bfloat16 h0 = __float2bfloat16(v.x), h1 = __float2bfloat16(v.y);
    __nv_bfloat16 h2 = __float2bfloat16(v.z), h3 = __float2bfloat16(v.w);
    __nv_bfloat16 l0 = __float2bfloat16(v.x - __bfloat162float(h0));
    __nv_bfloat16 l1 = __float2bfloat16(v.y - __bfloat162float(h1));
    __nv_bfloat16 l2 = __float2bfloat16(v.z - __bfloat162float(h2));
    __nv_bfloat16 l3 = __float2bfloat16(v.w - __bfloat162float(h3));
    ((__nv_bfloat162*)g_Eh)[i / 2]     = __nv_bfloat162(h0, h1);
    ((__nv_bfloat162*)g_Eh)[i / 2 + 1] = __nv_bfloat162(h2, h3);
    ((__nv_bfloat162*)g_El)[i / 2]     = __nv_bfloat162(l0, l1);
    ((__nv_bfloat162*)g_El)[i / 2 + 1] = __nv_bfloat162(l2, l3);
}
__global__ void zsq_kernel(const float* __restrict__ x) {
    int warp = (blockIdx.x * blockDim.x + threadIdx.x) >> 5;
    int lane = threadIdx.x & 31;
    if (warp >= M_ROWS) return;
    const float* r = x + (size_t)warp * D_DIM;
    float s = 0.f;
#pragma unroll
    for (int i = 0; i < D_DIM / 32; i++) { float v = r[lane + 32 * i]; s = fmaf(v, v, s); }
#pragma unroll
    for (int o = 16; o; o >>= 1) s += __shfl_xor_sync(0xffffffffu, s, o);
    if (lane == 0) g_zsq[warp] = s;
}
__global__ void esq_kernel(const float* __restrict__ x) {
    int warp = (blockIdx.x * blockDim.x + threadIdx.x) >> 5;
    int lane = threadIdx.x & 31;
    if (warp >= K_CODES) return;
    const float* r = x + (size_t)warp * D_DIM;
    float s = 0.f;
#pragma unroll
    for (int i = 0; i < D_DIM / 32; i++) { float v = r[lane + 32 * i]; s = fmaf(v, v, s); }
#pragma unroll
    for (int o = 16; o; o >>= 1) s += __shfl_xor_sync(0xffffffffu, s, o);
    if (lane == 0) g_esq[warp] = s;
}

// ---------------- main kernel ----------------
__global__ __launch_bounds__(NTHREADS, 1) void vq_main_kernel(
    const float* __restrict__ Z, const float* __restrict__ E,
    float* __restrict__ out) {

    extern __shared__ char smem[];
    const uint32_t sb = smem_u32(smem);
    const int t      = threadIdx.x;
    const int wid    = t >> 5;
    const int lane   = t & 31;
    const int warp_m = wid >> 2;   // 0..1
    const int warp_n = wid & 3;    // 0..3
    const int m0     = blockIdx.x * BM;

    float* esq_s = (float*)(smem + OFF_ESQ);
    float* red_v = (float*)(smem + OFF_REDV);
    int*   red_i = (int*)(smem + OFF_REDI);
    int*   idx_s = (int*)(smem + OFF_IDX);
    float* wsum  = (float*)(smem + OFF_WSUM);

    for (int i = t; i < K_CODES; i += NTHREADS) esq_s[i] = g_esq[i];

    // resident A (Zh, Zl): 8192 uint4, swizzled 16B chunks (32 per 512B row)
    const uint4* Zh4 = (const uint4*)g_Zh;
    const uint4* Zl4 = (const uint4*)g_Zl;
    for (int i = t; i < 8192; i += NTHREADS) {
        int mat = i >> 12;
        int j   = i & 4095;
        int row = j >> 5, ch = j & 31;
        uint4 v = (mat ? Zl4 : Zh4)[(size_t)(m0 + row) * 32 + ch];
        *(uint4*)(smem + (mat ? OFF_AL : OFF_A) + row * 512 + ((ch ^ (row & 7)) * 16)) = v;
    }

    float zsv[4][2];
#pragma unroll
    for (int mi = 0; mi < 4; mi++)
#pragma unroll
        for (int h = 0; h < 2; h++)
            zsv[mi][h] = g_zsq[m0 + warp_m * 64 + mi * 16 + (lane >> 2) + 8 * h];

    __syncthreads();

    float bestv = 3.4e38f;
    int   besti = 0;

    const uint4* Eh4 = (const uint4*)g_Eh;
    const uint4* El4 = (const uint4*)g_El;

    for (int nt = 0; nt < NCHUNK; nt++) {
        const int n0 = nt * BN;

        float c[4][4][4];
#pragma unroll
        for (int mi = 0; mi < 4; mi++)
#pragma unroll
            for (int ni = 0; ni < 4; ni++)
#pragma unroll
                for (int q = 0; q < 4; q++) c[mi][ni][q] = 0.f;

        // stage slice 0 into buf0
#pragma unroll
        for (int j = 0; j < 8; j++) {
            int i = t + j * NTHREADS;
            int mat = i >> 10, jj = i & 1023;
            int row = jj >> 3, ch = jj & 7;
            uint4 v = (mat ? El4 : Eh4)[(size_t)(n0 + row) * 32 + ch];
            *(uint4*)(smem + OFF_B + mat * 16384 + row * 128 + ((ch ^ (row & 7)) * 16)) = v;
        }
        __syncthreads();

#pragma unroll 1
        for (int s = 0; s < 4; s++) {
            uint4 nx[8];
            if (s < 3) {
#pragma unroll
                for (int j = 0; j < 8; j++) {
                    int i = t + j * NTHREADS;
                    int mat = i >> 10, jj = i & 1023;
                    int row = jj >> 3, ch = jj & 7;
                    nx[j] = (mat ? El4 : Eh4)[(size_t)(n0 + row) * 32 + (s + 1) * 8 + ch];
                }
            }
            const uint32_t bb = sb + OFF_B + (s & 1) * 32768;
#pragma unroll
            for (int tk = 0; tk < 4; tk++) {
                const int kg = s * 4 + tk;
                uint32_t ah[4][4], al[4][4];
#pragma unroll
                for (int mi = 0; mi < 4; mi++) {
                    int row = warp_m * 64 + mi * 16 + (lane & 15);
                    int ch  = kg * 2 + (lane >> 4);
                    uint32_t adr = sb + OFF_A + row * 512 + ((ch ^ (row & 7)) * 16);
                    ldsm_x4(ah[mi][0], ah[mi][1], ah[mi][2], ah[mi][3], adr);
                    ldsm_x4(al[mi][0], al[mi][1], al[mi][2], al[mi][3], adr + 65536);
                }
                uint32_t bh[4][2], bl[4][2];
#pragma unroll
                for (int ni = 0; ni < 4; ni++) {
                    int rn = warp_n * 32 + ni * 8 + (lane & 7);
                    int ch = tk * 2 + ((lane >> 3) & 1);
                    uint32_t adr = bb + rn * 128 + ((ch ^ (rn & 7)) * 16);
                    ldsm_x2(bh[ni][0], bh[ni][1], adr);
                    ldsm_x2(bl[ni][0], bl[ni][1], adr + 16384);
                }
#pragma unroll
                for (int mi = 0; mi < 4; mi++)
#pragma unroll
                    for (int ni = 0; ni < 4; ni++) {
                        mma16816(c[mi][ni], ah[mi], bh[ni]);
                        mma16816(c[mi][ni], ah[mi], bl[ni]);
                        mma16816(c[mi][ni], al[mi], bh[ni]);
                    }
            }
            if (s < 3) {
#pragma unroll
                for (int j = 0; j < 8; j++) {
                    int i = t + j * NTHREADS;
                    int mat = i >> 10, jj = i & 1023;
                    int row = jj >> 3, ch = jj & 7;
                    *(uint4*)(smem + OFF_B + ((s + 1) & 1) * 32768 + mat * 16384 +
                              row * 128 + ((ch ^ (row & 7)) * 16)) = nx[j];
                }
            }
            __syncthreads();
        }

        // ---- epilogue ----
#pragma unroll
        for (int mi = 0; mi < 4; mi++)
#pragma unroll
            for (int h = 0; h < 2; h++) {
                float v = 3.4e38f;
                int   bi = 0;
#pragma unroll
                for (int ni = 0; ni < 4; ni++)
#pragma unroll
                    for (int jc = 0; jc < 2; jc++) {
                        int n = n0 + warp_n * 32 + ni * 8 + (lane & 3) * 2 + jc;
                        float s2 = zsv[mi][h] + esq_s[n];
                        float d  = fmaf(-2.0f, c[mi][ni][h * 2 + jc], s2);
                        if (d < v) { v = d; bi = n; }
                    }
#pragma unroll
                for (int off = 1; off <= 2; off <<= 1) {
                    float ov = __shfl_xor_sync(0xffffffffu, v, off);
                    int   oi = __shfl_xor_sync(0xffffffffu, bi, off);
                    if (ov < v || (ov == v && oi < bi)) { v = ov; bi = oi; }
                }
                if ((lane & 3) == 0) {
                    int rl = warp_m * 64 + mi * 16 + (lane >> 2) + 8 * h;
                    red_v[warp_n * 128 + rl] = v;
                    red_i[warp_n * 128 + rl] = bi;
                }
            }
        __syncthreads();
        if (t < BM) {
            float v = red_v[t];
            int   bi = red_i[t];
#pragma unroll
            for (int w = 1; w < 4; w++) {
                float ov = red_v[w * 128 + t];
                int   oi = red_i[w * 128 + t];
                if (ov < v || (ov == v && oi < bi)) { v = ov; bi = oi; }
            }
            if (v < bestv || (v == bestv && bi < besti)) { bestv = v; besti = bi; }
        }
        __syncthreads();
    }

    if (t < BM) {
        idx_s[t] = besti;
        out[(size_t)M_ROWS * D_DIM + 1 + m0 + t] = (float)besti;
    }
    __syncthreads();

    const float4* Zf4 = (const float4*)Z;
    const float4* Ef4 = (const float4*)E;
    float4* Of4 = (float4*)out;
    float part = 0.f;
    for (int i = t; i < BM * (D_DIM / 4); i += NTHREADS) {
        int m = i >> 6, cidx = i & 63;
        int bi = idx_s[m];
        float4 e = Ef4[(size_t)bi * (D_DIM / 4) + cidx];
        float4 z = Zf4[(size_t)(m0 + m) * (D_DIM / 4) + cidx];
        Of4[(size_t)(m0 + m) * (D_DIM / 4) + cidx] = e;
        float dx = e.x - z.x, dy = e.y - z.y, dz = e.z - z.z, dw = e.w - z.w;
        part = fmaf(dx, dx, part); part = fmaf(dy, dy, part);
        part = fmaf(dz, dz, part); part = fmaf(dw, dw, part);
    }
#pragma unroll
    for (int o = 16; o; o >>= 1) part += __shfl_xor_sync(0xffffffffu, part, o);
    if (lane == 0) wsum[wid] = part;
    __syncthreads();
    if (t == 0) {
        float s = 0.f;
#pragma unroll
        for (int w = 0; w < NTHREADS / 32; w++) s += wsum[w];
        atomicAdd(&g_loss, (double)s);
    }
}

__global__ void finalize_kernel(float* __restrict__ out) {
    out[(size_t)M_ROWS * D_DIM] =
        (float)(1.25 * g_loss / ((double)M_ROWS * (double)D_DIM));
}

// ---------------------------------------------------------------------------
extern "C" void kernel_launch(void* const* d_in, const int* in_sizes, int n_in,
                              void* d_out, int out_size) {
    (void)in_sizes; (void)n_in; (void)out_size;
    const float* z = (const float*)d_in[0];
    const float* e = (const float*)d_in[1];
    float* out = (float*)d_out;

    cudaFuncSetAttribute(vq_main_kernel,
                         cudaFuncAttributeMaxDynamicSharedMemorySize, SMEM_BYTES);

    split_z_kernel<<<M_ROWS * D_DIM / 4 / 256, 256>>>(z);
    split_e_kernel<<<K_CODES * D_DIM / 4 / 256, 256>>>(e);
    zsq_kernel<<<M_ROWS / 8, 256>>>(z);
    esq_kernel<<<K_CODES / 8, 256>>>(e);
    vq_main_kernel<<<M_ROWS / BM, NTHREADS, SMEM_BYTES>>>(z, e, out);
    finalize_kernel<<<1, 1>>>(out);
}

// round 6
// speedup vs baseline: 6.2038x; 1.8607x over previous
#include <cuda_runtime.h>
#include <cuda_bf16.h>
#include <cstdint>

// VQ-VAE quantizer — 1-term bf16 HMMA approx distances + exact fp32
// candidate refinement.
//   d_hat = fl(zsq+esq) - 2*(Zh·Eh^T)      (bf16 MMA, fp32 accum)
//   candidates: d_hat <= runmin + MARGIN   (provably contains true argmin)
//   refine: exact fp32 dot from original Z,E; argmin w/ lowest-index ties.

#define M_ROWS  65536
#define K_CODES 2048
#define D_DIM   256
#define BM      128
#define BN      128
#define NCHUNK  (K_CODES / BN)   // 16
#define NTHREADS 256
#define MAXC    16
#define MARGIN  6e-4f

// smem layout (dynamic)
#define OFF_REDV  0        // [4][128] float = 2048
#define OFF_RUNM  2048     // 128 float
#define OFF_IDX   2560     // 128 int
#define OFF_CNT   3072     // 128 int
#define OFF_WSUM  3584     // 8 float
#define OFF_CAND  4096     // 128*16 int = 8192
#define OFF_A     12288    // Ah 64KB
#define OFF_B     77824    // 2 x 16KB
#define SMEM_BYTES 110592

__device__ float  g_zsq[M_ROWS];
__device__ float  g_esq[K_CODES];
__device__ double g_loss;
__device__ __nv_bfloat16 g_Zh[(size_t)M_ROWS * D_DIM];
__device__ __nv_bfloat16 g_Eh[(size_t)K_CODES * D_DIM];

__device__ __forceinline__ uint32_t smem_u32(const void* p) {
    uint32_t a;
    asm("{ .reg .u64 t; cvta.to.shared.u64 t, %1; cvt.u32.u64 %0, t; }" : "=r"(a) : "l"(p));
    return a;
}
__device__ __forceinline__ void ldsm_x4(uint32_t& r0, uint32_t& r1, uint32_t& r2,
                                        uint32_t& r3, uint32_t addr) {
    asm volatile("ldmatrix.sync.aligned.m8n8.x4.shared.b16 {%0,%1,%2,%3}, [%4];"
                 : "=r"(r0), "=r"(r1), "=r"(r2), "=r"(r3) : "r"(addr));
}
__device__ __forceinline__ void ldsm_x2(uint32_t& r0, uint32_t& r1, uint32_t addr) {
    asm volatile("ldmatrix.sync.aligned.m8n8.x2.shared.b16 {%0,%1}, [%2];"
                 : "=r"(r0), "=r"(r1) : "r"(addr));
}
__device__ __forceinline__ void mma16816(float* c, const uint32_t* a, const uint32_t* b) {
    asm volatile("mma.sync.aligned.m16n8k16.row.col.f32.bf16.bf16.f32 "
                 "{%0,%1,%2,%3}, {%4,%5,%6,%7}, {%8,%9}, {%0,%1,%2,%3};"
                 : "+f"(c[0]), "+f"(c[1]), "+f"(c[2]), "+f"(c[3])
                 : "r"(a[0]), "r"(a[1]), "r"(a[2]), "r"(a[3]), "r"(b[0]), "r"(b[1]));
}

// ---------------- pre-kernels ----------------
__global__ void cvt_z_kernel(const float* __restrict__ z) {
    size_t i = ((size_t)blockIdx.x * 256 + threadIdx.x) * 4;
    float4 v = *(const float4*)(z + i);
    ((__nv_bfloat162*)g_Zh)[i / 2]     = __nv_bfloat162(__float2bfloat16(v.x), __float2bfloat16(v.y));
    ((__nv_bfloat162*)g_Zh)[i / 2 + 1] = __nv_bfloat162(__float2bfloat16(v.z), __float2bfloat16(v.w));
}
__global__ void cvt_e_kernel(const float* __restrict__ e) {
    if (blockIdx.x == 0 && threadIdx.x == 0) g_loss = 0.0;
    size_t i = ((size_t)blockIdx.x * 256 + threadIdx.x) * 4;
    float4 v = *(const float4*)(e + i);
    ((__nv_bfloat162*)g_Eh)[i / 2]     = __nv_bfloat162(__float2bfloat16(v.x), __float2bfloat16(v.y));
    ((__nv_bfloat162*)g_Eh)[i / 2 + 1] = __nv_bfloat162(__float2bfloat16(v.z), __float2bfloat16(v.w));
}
__global__ void zsq_kernel(const float* __restrict__ x) {
    int warp = (blockIdx.x * blockDim.x + threadIdx.x) >> 5;
    int lane = threadIdx.x & 31;
    if (warp >= M_ROWS) return;
    const float* r = x + (size_t)warp * D_DIM;
    float s = 0.f;
#pragma unroll
    for (int i = 0; i < D_DIM / 32; i++) { float v = r[lane + 32 * i]; s = fmaf(v, v, s); }
#pragma unroll
    for (int o = 16; o; o >>= 1) s += __shfl_xor_sync(0xffffffffu, s, o);
    if (lane == 0) g_zsq[warp] = s;
}
__global__ void esq_kernel(const float* __restrict__ x) {
    int warp = (blockIdx.x * blockDim.x + threadIdx.x) >> 5;
    int lane = threadIdx.x & 31;
    if (warp >= K_CODES) return;
    const float* r = x + (size_t)warp * D_DIM;
    float s = 0.f;
#pragma unroll
    for (int i = 0; i < D_DIM / 32; i++) { float v = r[lane + 32 * i]; s = fmaf(v, v, s); }
#pragma unroll
    for (int o = 16; o; o >>= 1) s += __shfl_xor_sync(0xffffffffu, s, o);
    if (lane == 0) g_esq[warp] = s;
}

// ---------------- main kernel ----------------
__global__ __launch_bounds__(NTHREADS, 2) void vq_main_kernel(
    const float* __restrict__ Z, const float* __restrict__ E,
    float* __restrict__ out) {

    extern __shared__ char smem[];
    const uint32_t sb = smem_u32(smem);
    const int t      = threadIdx.x;
    const int wid    = t >> 5;
    const int lane   = t & 31;
    const int warp_m = wid >> 2;   // 0..1
    const int warp_n = wid & 3;    // 0..3
    const int m0     = blockIdx.x * BM;

    float* red_v  = (float*)(smem + OFF_REDV);
    float* runm   = (float*)(smem + OFF_RUNM);
    int*   idx_s  = (int*)(smem + OFF_IDX);
    int*   cnt_s  = (int*)(smem + OFF_CNT);
    float* wsum   = (float*)(smem + OFF_WSUM);
    int*   cand   = (int*)(smem + OFF_CAND);

    // resident A (Zh): 4096 uint4, swizzled 16B chunks (32 per 512B row)
    const uint4* Zh4 = (const uint4*)g_Zh;
    for (int i = t; i < 4096; i += NTHREADS) {
        int row = i >> 5, ch = i & 31;
        uint4 v = Zh4[(size_t)(m0 + row) * 32 + ch];
        *(uint4*)(smem + OFF_A + row * 512 + ((ch ^ (row & 7)) * 16)) = v;
    }
    if (t < BM) { runm[t] = 3.4e38f; cnt_s[t] = 0; }

    float zsv[4][2];
#pragma unroll
    for (int mi = 0; mi < 4; mi++)
#pragma unroll
        for (int h = 0; h < 2; h++)
            zsv[mi][h] = g_zsq[m0 + warp_m * 64 + mi * 16 + (lane >> 2) + 8 * h];

    __syncthreads();

    const uint4* Eh4 = (const uint4*)g_Eh;

    for (int nt = 0; nt < NCHUNK; nt++) {
        const int n0 = nt * BN;

        float c[4][4][4];
#pragma unroll
        for (int mi = 0; mi < 4; mi++)
#pragma unroll
            for (int ni = 0; ni < 4; ni++)
#pragma unroll
                for (int q = 0; q < 4; q++) c[mi][ni][q] = 0.f;

        // stage slice 0 into buf0 (Bh only: 1024 uint4)
#pragma unroll
        for (int j = 0; j < 4; j++) {
            int i = t + j * NTHREADS;
            int row = i >> 3, ch = i & 7;
            uint4 v = Eh4[(size_t)(n0 + row) * 32 + ch];
            *(uint4*)(smem + OFF_B + row * 128 + ((ch ^ (row & 7)) * 16)) = v;
        }
        __syncthreads();

#pragma unroll 1
        for (int s = 0; s < 4; s++) {
            uint4 nx[4];
            if (s < 3) {
#pragma unroll
                for (int j = 0; j < 4; j++) {
                    int i = t + j * NTHREADS;
                    int row = i >> 3, ch = i & 7;
                    nx[j] = Eh4[(size_t)(n0 + row) * 32 + (s + 1) * 8 + ch];
                }
            }
            const uint32_t bb = sb + OFF_B + (s & 1) * 16384;
#pragma unroll
            for (int tk = 0; tk < 4; tk++) {
                const int kg = s * 4 + tk;
                uint32_t ah[4][4];
#pragma unroll
                for (int mi = 0; mi < 4; mi++) {
                    int row = warp_m * 64 + mi * 16 + (lane & 15);
                    int ch  = kg * 2 + (lane >> 4);
                    uint32_t adr = sb + OFF_A + row * 512 + ((ch ^ (row & 7)) * 16);
                    ldsm_x4(ah[mi][0], ah[mi][1], ah[mi][2], ah[mi][3], adr);
                }
                uint32_t bh[4][2];
#pragma unroll
                for (int ni = 0; ni < 4; ni++) {
                    int rn = warp_n * 32 + ni * 8 + (lane & 7);
                    int ch = tk * 2 + ((lane >> 3) & 1);
                    uint32_t adr = bb + rn * 128 + ((ch ^ (rn & 7)) * 16);
                    ldsm_x2(bh[ni][0], bh[ni][1], adr);
                }
#pragma unroll
                for (int mi = 0; mi < 4; mi++)
#pragma unroll
                    for (int ni = 0; ni < 4; ni++)
                        mma16816(c[mi][ni], ah[mi], bh[ni]);
            }
            if (s < 3) {
#pragma unroll
                for (int j = 0; j < 4; j++) {
                    int i = t + j * NTHREADS;
                    int row = i >> 3, ch = i & 7;
                    *(uint4*)(smem + OFF_B + ((s + 1) & 1) * 16384 +
                              row * 128 + ((ch ^ (row & 7)) * 16)) = nx[j];
                }
            }
            __syncthreads();
        }

        // ---- pass A: chunk-local per-row min of d_hat ----
#pragma unroll
        for (int mi = 0; mi < 4; mi++)
#pragma unroll
            for (int h = 0; h < 2; h++) {
                float v = 3.4e38f;
#pragma unroll
                for (int ni = 0; ni < 4; ni++)
#pragma unroll
                    for (int jc = 0; jc < 2; jc++) {
                        int n = n0 + warp_n * 32 + ni * 8 + (lane & 3) * 2 + jc;
                        float d = fmaf(-2.0f, c[mi][ni][h * 2 + jc], zsv[mi][h] + g_esq[n]);
                        v = fminf(v, d);
                    }
#pragma unroll
                for (int off = 1; off <= 2; off <<= 1)
                    v = fminf(v, __shfl_xor_sync(0xffffffffu, v, off));
                if ((lane & 3) == 0) {
                    int rl = warp_m * 64 + mi * 16 + (lane >> 2) + 8 * h;
                    red_v[warp_n * 128 + rl] = v;
                }
            }
        __syncthreads();
        if (t < BM) {
            float v = red_v[t];
#pragma unroll
            for (int w = 1; w < 4; w++) v = fminf(v, red_v[w * 128 + t]);
            runm[t] = fminf(runm[t], v);
        }
        __syncthreads();

        // ---- pass B: collect candidates within margin of running min ----
#pragma unroll
        for (int mi = 0; mi < 4; mi++)
#pragma unroll
            for (int h = 0; h < 2; h++) {
                int rl = warp_m * 64 + mi * 16 + (lane >> 2) + 8 * h;
                float thr = runm[rl] + MARGIN;
#pragma unroll
                for (int ni = 0; ni < 4; ni++)
#pragma unroll
                    for (int jc = 0; jc < 2; jc++) {
                        int n = n0 + warp_n * 32 + ni * 8 + (lane & 3) * 2 + jc;
                        float d = fmaf(-2.0f, c[mi][ni][h * 2 + jc], zsv[mi][h] + g_esq[n]);
                        if (d <= thr) {
                            int pos = atomicAdd(&cnt_s[rl], 1);
                            if (pos < MAXC) cand[rl * MAXC + pos] = n;
                        }
                    }
            }
        __syncthreads();
    }

    // ---- exact fp32 refinement: one warp per 16 rows ----
    for (int rr = 0; rr < BM / 8; rr++) {
        int r = wid * (BM / 8) + rr;
        const float* zrow = Z + (size_t)(m0 + r) * D_DIM;
        float zreg[8];
#pragma unroll
        for (int j = 0; j < 8; j++) zreg[j] = zrow[lane + 32 * j];
        float zs = g_zsq[m0 + r];
        int cnt = cnt_s[r];
        float bv = 3.4e38f;
        int   bi = 0x7fffffff;
        if (cnt <= MAXC) {
            for (int ci = 0; ci < cnt; ci++) {
                int n = cand[r * MAXC + ci];
                const float* erow = E + (size_t)n * D_DIM;
                float p = 0.f;
#pragma unroll
                for (int j = 0; j < 8; j++) p = fmaf(zreg[j], erow[lane + 32 * j], p);
#pragma unroll
                for (int o = 16; o; o >>= 1) p += __shfl_xor_sync(0xffffffffu, p, o);
                float d = fmaf(-2.0f, p, zs + g_esq[n]);
                if (d < bv || (d == bv && n < bi)) { bv = d; bi = n; }
            }
        } else {
            // overflow fallback: exact scan of all codes (effectively never)
            for (int n = 0; n < K_CODES; n++) {
                const float* erow = E + (size_t)n * D_DIM;
                float p = 0.f;
#pragma unroll
                for (int j = 0; j < 8; j++) p = fmaf(zreg[j], erow[lane + 32 * j], p);
#pragma unroll
                for (int o = 16; o; o >>= 1) p += __shfl_xor_sync(0xffffffffu, p, o);
                float d = fmaf(-2.0f, p, zs + g_esq[n]);
                if (d < bv) { bv = d; bi = n; }
            }
        }
        if (lane == 0) {
            idx_s[r] = bi;
            out[(size_t)M_ROWS * D_DIM + 1 + m0 + r] = (float)bi;
        }
    }
    __syncthreads();

    // ---- gather z_q + loss partial (exact fp32 from originals) ----
    const float4* Zf4 = (const float4*)Z;
    const float4* Ef4 = (const float4*)E;
    float4* Of4 = (float4*)out;
    float part = 0.f;
    for (int i = t; i < BM * (D_DIM / 4); i += NTHREADS) {
        int m = i >> 6, cidx = i & 63;
        int bi = idx_s[m];
        float4 e = Ef4[(size_t)bi * (D_DIM / 4) + cidx];
        float4 z = Zf4[(size_t)(m0 + m) * (D_DIM / 4) + cidx];
        Of4[(size_t)(m0 + m) * (D_DIM / 4) + cidx] = e;
        float dx = e.x - z.x, dy = e.y - z.y, dz = e.z - z.z, dw = e.w - z.w;
        part = fmaf(dx, dx, part); part = fmaf(dy, dy, part);
        part = fmaf(dz, dz, part); part = fmaf(dw, dw, part);
    }
#pragma unroll
    for (int o = 16; o; o >>= 1) part += __shfl_xor_sync(0xffffffffu, part, o);
    if (lane == 0) wsum[wid] = part;
    __syncthreads();
    if (t == 0) {
        float s = 0.f;
#pragma unroll
        for (int w = 0; w < NTHREADS / 32; w++) s += wsum[w];
        atomicAdd(&g_loss, (double)s);
    }
}

__global__ void finalize_kernel(float* __restrict__ out) {
    out[(size_t)M_ROWS * D_DIM] =
        (float)(1.25 * g_loss / ((double)M_ROWS * (double)D_DIM));
}

// ---------------------------------------------------------------------------
extern "C" void kernel_launch(void* const* d_in, const int* in_sizes, int n_in,
                              void* d_out, int out_size) {
    (void)in_sizes; (void)n_in; (void)out_size;
    const float* z = (const float*)d_in[0];
    const float* e = (const float*)d_in[1];
    float* out = (float*)d_out;

    cudaFuncSetAttribute(vq_main_kernel,
                         cudaFuncAttributeMaxDynamicSharedMemorySize, SMEM_BYTES);

    cvt_z_kernel<<<M_ROWS * D_DIM / 4 / 256, 256>>>(z);
    cvt_e_kernel<<<K_CODES * D_DIM / 4 / 256, 256>>>(e);
    zsq_kernel<<<M_ROWS / 8, 256>>>(z);
    esq_kernel<<<K_CODES / 8, 256>>>(e);
    vq_main_kernel<<<M_ROWS / BM, NTHREADS, SMEM_BYTES>>>(z, e, out);
    finalize_kernel<<<1, 1>>>(out);
}